// round 14
// baseline (speedup 1.0000x reference)
#include <cuda_runtime.h>
#include <cuda_bf16.h>
#include <cuda_fp16.h>
#include <cstdint>

#define NN 100000
#define EE 1600000
#define CC 64
#define DD 512
#define KHOPS 10

#define SCAN_B 512                      // elements per scan block
#define SCAN_NB ((NN + SCAN_B - 1) / SCAN_B)

// ---- device scratch ----
__device__ __half g_H[KHOPS * (size_t)NN * CC];  // hop features 0..9, fp16 (hop 10 lazy)
__device__ int   g_deg[NN];
__device__ int   g_rowptr[NN + 1];
__device__ int   g_cursor[NN];
__device__ int   g_part[SCAN_NB];
__device__ int2  g_edges[EE];       // .x = src, .y = float bits of weight

// ---------------- preprocessing: CSR by destination ----------------

__global__ void zero_kernel(int n) {
    int i = blockIdx.x * blockDim.x + threadIdx.x;
    if (i < n) g_deg[i] = 0;
}

__global__ void count_kernel(const int* __restrict__ dst, int e) {
    int i = blockIdx.x * blockDim.x + threadIdx.x;
    if (i < e) atomicAdd(&g_deg[dst[i]], 1);
}

__global__ void scan_partial_kernel(int n) {
    __shared__ int s[256];
    int b = blockIdx.x, t = threadIdx.x;
    int i0 = b * SCAN_B + t * 2;
    int v = 0;
    if (i0 < n)     v += g_deg[i0];
    if (i0 + 1 < n) v += g_deg[i0 + 1];
    s[t] = v;
    __syncthreads();
    for (int off = 128; off; off >>= 1) {
        if (t < off) s[t] += s[t + off];
        __syncthreads();
    }
    if (t == 0) g_part[b] = s[0];
}

__global__ void scan_top_kernel(int nb, int n) {
    __shared__ int s[256];
    int t = threadIdx.x;
    int v = (t < nb) ? g_part[t] : 0;
    s[t] = v;
    __syncthreads();
    for (int off = 1; off < 256; off <<= 1) {
        int add = (t >= off) ? s[t - off] : 0;
        __syncthreads();
        s[t] += add;
        __syncthreads();
    }
    if (t < nb) g_part[t] = s[t] - v;        // exclusive
    if (t == 255) g_rowptr[n] = s[255];      // total
}

__global__ void rowptr_kernel(int n) {
    __shared__ int s[256];
    int b = blockIdx.x, t = threadIdx.x;
    int i0 = b * SCAN_B + t * 2;
    int d0 = (i0 < n)     ? g_deg[i0]     : 0;
    int d1 = (i0 + 1 < n) ? g_deg[i0 + 1] : 0;
    int pair = d0 + d1;
    s[t] = pair;
    __syncthreads();
    for (int off = 1; off < 256; off <<= 1) {
        int add = (t >= off) ? s[t - off] : 0;
        __syncthreads();
        s[t] += add;
        __syncthreads();
    }
    int base = g_part[b] + s[t] - pair;      // exclusive prefix for i0
    if (i0 < n)     { g_rowptr[i0] = base;          g_cursor[i0] = base; }
    if (i0 + 1 < n) { g_rowptr[i0 + 1] = base + d0; g_cursor[i0 + 1] = base + d0; }
}

__global__ void fill_kernel(const int* __restrict__ src, const int* __restrict__ dst,
                            const float* __restrict__ w, int e) {
    int i = blockIdx.x * blockDim.x + threadIdx.x;
    if (i < e) {
        int pos = atomicAdd(&g_cursor[dst[i]], 1);
        g_edges[pos] = make_int2(src[i], __float_as_int(w[i]));
    }
}

// ---------------- tensor-core MLP: h = relu(relu(x@W1)@W2) ----------------
// bf16 double-split (hi+lo), 3x mma.sync.m16n8k16 => ~fp32 precision.
// 256-row block tile (best-measured config, R11).
#define MLP_SMEM 83968
#define S1_STRIDE 40
#define S2_STRIDE 72

__device__ __forceinline__ void mma_bf16(float* c, uint32_t a0, uint32_t a1,
                                         uint32_t a2, uint32_t a3,
                                         uint32_t b0, uint32_t b1) {
    asm volatile(
        "mma.sync.aligned.m16n8k16.row.col.f32.bf16.bf16.f32 "
        "{%0,%1,%2,%3}, {%4,%5,%6,%7}, {%8,%9}, {%0,%1,%2,%3};\n"
        : "+f"(c[0]), "+f"(c[1]), "+f"(c[2]), "+f"(c[3])
        : "r"(a0), "r"(a1), "r"(a2), "r"(a3), "r"(b0), "r"(b1));
}

__device__ __forceinline__ void split2(float x, float y, uint32_t& hi, uint32_t& lo) {
    __nv_bfloat162 h2 = __floats2bfloat162_rn(x, y);
    float rx = x - __bfloat162float(h2.x);
    float ry = y - __bfloat162float(h2.y);
    __nv_bfloat162 l2 = __floats2bfloat162_rn(rx, ry);
    hi = *(uint32_t*)&h2;
    lo = *(uint32_t*)&l2;
}

__global__ __launch_bounds__(256) void mlp_mma_kernel(const float* __restrict__ x,
                                                      const float* __restrict__ W1,
                                                      const float* __restrict__ W2,
                                                      __half* __restrict__ h_out,
                                                      int n) {
    extern __shared__ char sm[];
    __nv_bfloat16* uHi = (__nv_bfloat16*)sm;
    __nv_bfloat16* uLo = (__nv_bfloat16*)(sm + 36864);
    __nv_bfloat16* bHi = (__nv_bfloat16*)(sm + 73728);
    __nv_bfloat16* bLo = (__nv_bfloat16*)(sm + 78848);

    int tid  = threadIdx.x;
    int lane = tid & 31;
    int warp = tid >> 5;
    int g  = lane >> 2;
    int tg = lane & 3;
    int row0 = blockIdx.x * 256;
    int warpRow = warp * 32;

    float acc[2][8][4];
#pragma unroll
    for (int rg = 0; rg < 2; rg++)
#pragma unroll
        for (int nt = 0; nt < 8; nt++)
#pragma unroll
            for (int q = 0; q < 4; q++) acc[rg][nt][q] = 0.f;

    // ---- stage 1: h1 = relu(x @ W1), K = 512 in 16 chunks of 32 ----
    for (int kc = 0; kc < 16; kc++) {
        int k0 = kc * 32;
        __syncthreads();
        for (int p = tid; p < 2048; p += 256) {
            int r = p >> 3, c4 = p & 7;
            float4 v = make_float4(0.f, 0.f, 0.f, 0.f);
            if (row0 + r < n)
                v = *(const float4*)&x[(size_t)(row0 + r) * DD + k0 + c4 * 4];
            uint32_t h0, l0, h1v, l1v;
            split2(v.x, v.y, h0, l0);
            split2(v.z, v.w, h1v, l1v);
            int base = r * S1_STRIDE + c4 * 4;
            *(uint32_t*)&uHi[base]     = h0;
            *(uint32_t*)&uHi[base + 2] = h1v;
            *(uint32_t*)&uLo[base]     = l0;
            *(uint32_t*)&uLo[base + 2] = l1v;
        }
        for (int p = tid; p < 512; p += 256) {
            int k = p >> 4, n4 = p & 15;
            float4 v = *(const float4*)&W1[(size_t)(k0 + k) * CC + n4 * 4];
            float vv[4] = {v.x, v.y, v.z, v.w};
#pragma unroll
            for (int j = 0; j < 4; j++) {
                int nn = n4 * 4 + j;
                __nv_bfloat16 h = __float2bfloat16(vv[j]);
                __nv_bfloat16 l = __float2bfloat16(vv[j] - __bfloat162float(h));
                bHi[nn * S1_STRIDE + k] = h;
                bLo[nn * S1_STRIDE + k] = l;
            }
        }
        __syncthreads();

#pragma unroll
        for (int ks = 0; ks < 2; ks++) {
            int kb = ks * 16;
            uint32_t aHi[2][4], aLo[2][4];
#pragma unroll
            for (int rg = 0; rg < 2; rg++) {
                int r = warpRow + rg * 16 + g;
                int i0 = r * S1_STRIDE + kb + tg * 2;
                int i1 = (r + 8) * S1_STRIDE + kb + tg * 2;
                aHi[rg][0] = *(uint32_t*)&uHi[i0];
                aHi[rg][1] = *(uint32_t*)&uHi[i1];
                aHi[rg][2] = *(uint32_t*)&uHi[i0 + 8];
                aHi[rg][3] = *(uint32_t*)&uHi[i1 + 8];
                aLo[rg][0] = *(uint32_t*)&uLo[i0];
                aLo[rg][1] = *(uint32_t*)&uLo[i1];
                aLo[rg][2] = *(uint32_t*)&uLo[i0 + 8];
                aLo[rg][3] = *(uint32_t*)&uLo[i1 + 8];
            }
#pragma unroll
            for (int nt = 0; nt < 8; nt++) {
                int bi = (nt * 8 + g) * S1_STRIDE + kb + tg * 2;
                uint32_t b0h = *(uint32_t*)&bHi[bi];
                uint32_t b1h = *(uint32_t*)&bHi[bi + 8];
                uint32_t b0l = *(uint32_t*)&bLo[bi];
                uint32_t b1l = *(uint32_t*)&bLo[bi + 8];
#pragma unroll
                for (int rg = 0; rg < 2; rg++) {
                    mma_bf16(acc[rg][nt], aHi[rg][0], aHi[rg][1], aHi[rg][2], aHi[rg][3], b0h, b1h);
                    mma_bf16(acc[rg][nt], aHi[rg][0], aHi[rg][1], aHi[rg][2], aHi[rg][3], b0l, b1l);
                    mma_bf16(acc[rg][nt], aLo[rg][0], aLo[rg][1], aLo[rg][2], aLo[rg][3], b0h, b1h);
                }
            }
        }
    }

    // ---- relu(h1) -> smem bf16 hi/lo, reset acc ----
    __syncthreads();
#pragma unroll
    for (int rg = 0; rg < 2; rg++) {
        int r1 = warpRow + rg * 16 + g;
        int r2 = r1 + 8;
#pragma unroll
        for (int nt = 0; nt < 8; nt++) {
            int col = nt * 8 + tg * 2;
            float v0 = fmaxf(acc[rg][nt][0], 0.f);
            float v1 = fmaxf(acc[rg][nt][1], 0.f);
            float v2 = fmaxf(acc[rg][nt][2], 0.f);
            float v3 = fmaxf(acc[rg][nt][3], 0.f);
            uint32_t h, l;
            split2(v0, v1, h, l);
            *(uint32_t*)&uHi[r1 * S2_STRIDE + col] = h;
            *(uint32_t*)&uLo[r1 * S2_STRIDE + col] = l;
            split2(v2, v3, h, l);
            *(uint32_t*)&uHi[r2 * S2_STRIDE + col] = h;
            *(uint32_t*)&uLo[r2 * S2_STRIDE + col] = l;
#pragma unroll
            for (int q = 0; q < 4; q++) acc[rg][nt][q] = 0.f;
        }
    }
    __syncthreads();

    // ---- stage 2: h = relu(h1 @ W2), K = 64 ----
    for (int c2 = 0; c2 < 2; c2++) {
        if (c2) __syncthreads();
        for (int p = tid; p < 512; p += 256) {
            int k = p >> 4, n4 = p & 15;
            float4 v = *(const float4*)&W2[(size_t)(c2 * 32 + k) * CC + n4 * 4];
            float vv[4] = {v.x, v.y, v.z, v.w};
#pragma unroll
            for (int j = 0; j < 4; j++) {
                int nn = n4 * 4 + j;
                __nv_bfloat16 h = __float2bfloat16(vv[j]);
                __nv_bfloat16 l = __float2bfloat16(vv[j] - __bfloat162float(h));
                bHi[nn * S1_STRIDE + k] = h;
                bLo[nn * S1_STRIDE + k] = l;
            }
        }
        __syncthreads();

#pragma unroll
        for (int ks = 0; ks < 2; ks++) {
            int kb = c2 * 32 + ks * 16;
            int kbb = ks * 16;
            uint32_t aHi[2][4], aLo[2][4];
#pragma unroll
            for (int rg = 0; rg < 2; rg++) {
                int r = warpRow + rg * 16 + g;
                int i0 = r * S2_STRIDE + kb + tg * 2;
                int i1 = (r + 8) * S2_STRIDE + kb + tg * 2;
                aHi[rg][0] = *(uint32_t*)&uHi[i0];
                aHi[rg][1] = *(uint32_t*)&uHi[i1];
                aHi[rg][2] = *(uint32_t*)&uHi[i0 + 8];
                aHi[rg][3] = *(uint32_t*)&uHi[i1 + 8];
                aLo[rg][0] = *(uint32_t*)&uLo[i0];
                aLo[rg][1] = *(uint32_t*)&uLo[i1];
                aLo[rg][2] = *(uint32_t*)&uLo[i0 + 8];
                aLo[rg][3] = *(uint32_t*)&uLo[i1 + 8];
            }
#pragma unroll
            for (int nt = 0; nt < 8; nt++) {
                int bi = (nt * 8 + g) * S1_STRIDE + kbb + tg * 2;
                uint32_t b0h = *(uint32_t*)&bHi[bi];
                uint32_t b1h = *(uint32_t*)&bHi[bi + 8];
                uint32_t b0l = *(uint32_t*)&bLo[bi];
                uint32_t b1l = *(uint32_t*)&bLo[bi + 8];
#pragma unroll
                for (int rg = 0; rg < 2; rg++) {
                    mma_bf16(acc[rg][nt], aHi[rg][0], aHi[rg][1], aHi[rg][2], aHi[rg][3], b0h, b1h);
                    mma_bf16(acc[rg][nt], aHi[rg][0], aHi[rg][1], aHi[rg][2], aHi[rg][3], b0l, b1l);
                    mma_bf16(acc[rg][nt], aLo[rg][0], aLo[rg][1], aLo[rg][2], aLo[rg][3], b0h, b1h);
                }
            }
        }
    }

    // ---- relu + store to h_out (fp16) ----
#pragma unroll
    for (int rg = 0; rg < 2; rg++) {
        int r1 = row0 + warpRow + rg * 16 + g;
        int r2 = r1 + 8;
#pragma unroll
        for (int nt = 0; nt < 8; nt++) {
            int col = nt * 8 + tg * 2;
            if (r1 < n)
                *(__half2*)&h_out[(size_t)r1 * CC + col] =
                    __floats2half2_rn(fmaxf(acc[rg][nt][0], 0.f), fmaxf(acc[rg][nt][1], 0.f));
            if (r2 < n)
                *(__half2*)&h_out[(size_t)r2 * CC + col] =
                    __floats2half2_rn(fmaxf(acc[rg][nt][2], 0.f), fmaxf(acc[rg][nt][3], 0.f));
        }
    }
}

// ---------------- SpMM hop: warp per dst row, fp16, 4 edges per LDG.128 ----------------
// Feature gathers: ld.global.cg (L2-only, no L1 allocation - negligible per-SM reuse).
// Edge reads: ld.global.cs (streaming, evict-first).
__device__ __forceinline__ void accum8(float* a, uint4 f, float ww) {
    float2 p0 = __half22float2(*(__half2*)&f.x);
    float2 p1 = __half22float2(*(__half2*)&f.y);
    float2 p2 = __half22float2(*(__half2*)&f.z);
    float2 p3 = __half22float2(*(__half2*)&f.w);
    a[0] = fmaf(ww, p0.x, a[0]); a[1] = fmaf(ww, p0.y, a[1]);
    a[2] = fmaf(ww, p1.x, a[2]); a[3] = fmaf(ww, p1.y, a[3]);
    a[4] = fmaf(ww, p2.x, a[4]); a[5] = fmaf(ww, p2.y, a[5]);
    a[6] = fmaf(ww, p3.x, a[6]); a[7] = fmaf(ww, p3.y, a[7]);
}

__global__ __launch_bounds__(256) void spmm_kernel(const __half* __restrict__ cur,
                                                   __half* __restrict__ nxt, int n) {
    int w = (blockIdx.x * blockDim.x + threadIdx.x) >> 5;
    int lane = threadIdx.x & 31;
    if (w >= n) return;
    int q  = lane >> 3;
    int c8 = (lane & 7) * 8;

    int beg = g_rowptr[w];
    int end = g_rowptr[w + 1];
    float a[8];
#pragma unroll
    for (int i = 0; i < 8; i++) a[i] = 0.f;

    int e = beg;
    for (; e + 7 < end; e += 8) {
        int2 ed0 = __ldcs(&g_edges[e + 2 * q]);
        int2 ed1 = __ldcs(&g_edges[e + 2 * q + 1]);
        uint4 f0 = __ldcg((const uint4*)&cur[(size_t)ed0.x * CC + c8]);
        uint4 f1 = __ldcg((const uint4*)&cur[(size_t)ed1.x * CC + c8]);
        accum8(a, f0, __int_as_float(ed0.y));
        accum8(a, f1, __int_as_float(ed1.y));
    }
    for (; e < end; e += 4) {
        int myE = e + q;
        if (myE < end) {
            int2 ed = __ldcs(&g_edges[myE]);
            uint4 f = __ldcg((const uint4*)&cur[(size_t)ed.x * CC + c8]);
            accum8(a, f, __int_as_float(ed.y));
        }
    }

#pragma unroll
    for (int i = 0; i < 8; i++) {
        a[i] += __shfl_xor_sync(0xffffffffu, a[i], 8);
        a[i] += __shfl_xor_sync(0xffffffffu, a[i], 16);
    }

    if (q == 0) {
        uint4 st;
        *(__half2*)&st.x = __floats2half2_rn(a[0], a[1]);
        *(__half2*)&st.y = __floats2half2_rn(a[2], a[3]);
        *(__half2*)&st.z = __floats2half2_rn(a[4], a[5]);
        *(__half2*)&st.w = __floats2half2_rn(a[6], a[7]);
        *(uint4*)&nxt[(size_t)w * CC + c8] = st;
    }
}

// ---------------- final: lazy hop-10 + gating + gather, requested nodes only ----------------
__global__ void final_kernel(const int* __restrict__ idx,
                             const float* __restrict__ wp,
                             float* __restrict__ out, int ni) {
    int w = (blockIdx.x * blockDim.x + threadIdx.x) >> 5;
    int lane = threadIdx.x & 31;
    if (w >= ni) return;
    int nd = idx[w];
    float wpx = __ldg(&wp[lane * 2]);
    float wpy = __ldg(&wp[lane * 2 + 1]);
    float ax = 0.f, ay = 0.f;

    // hops 0..9 from storage (fp16)
#pragma unroll
    for (int k = 0; k < KHOPS; k++) {
        uint32_t raw = __ldcg((const uint32_t*)&g_H[(size_t)k * NN * CC + (size_t)nd * CC + lane * 2]);
        float2 v = __half22float2(*(__half2*)&raw);
        float p = v.x * wpx + v.y * wpy;
#pragma unroll
        for (int o = 16; o; o >>= 1) p += __shfl_xor_sync(0xffffffffu, p, o);
        float s = 1.f / (1.f + __expf(-p));
        ax = fmaf(s, v.x, ax);
        ay = fmaf(s, v.y, ay);
    }

    // hop 10 computed lazily from H[9] (fp16 in, fp32 accum)
    const __half* __restrict__ H9 = g_H + (size_t)(KHOPS - 1) * NN * CC;
    int beg = g_rowptr[nd];
    int end = g_rowptr[nd + 1];
    float a0 = 0.f, a1 = 0.f;
    int e = beg;
    for (; e + 3 < end; e += 4) {
        int2 e0 = __ldcs(&g_edges[e]);
        int2 e1 = __ldcs(&g_edges[e + 1]);
        int2 e2 = __ldcs(&g_edges[e + 2]);
        int2 e3 = __ldcs(&g_edges[e + 3]);
        uint32_t r0 = __ldcg((const uint32_t*)&H9[(size_t)e0.x * CC + lane * 2]);
        uint32_t r1 = __ldcg((const uint32_t*)&H9[(size_t)e1.x * CC + lane * 2]);
        uint32_t r2 = __ldcg((const uint32_t*)&H9[(size_t)e2.x * CC + lane * 2]);
        uint32_t r3 = __ldcg((const uint32_t*)&H9[(size_t)e3.x * CC + lane * 2]);
        float2 v0 = __half22float2(*(__half2*)&r0);
        float2 v1 = __half22float2(*(__half2*)&r1);
        float2 v2 = __half22float2(*(__half2*)&r2);
        float2 v3 = __half22float2(*(__half2*)&r3);
        float w0 = __int_as_float(e0.y);
        float w1 = __int_as_float(e1.y);
        float w2 = __int_as_float(e2.y);
        float w3 = __int_as_float(e3.y);
        a0 = fmaf(w0, v0.x, a0); a1 = fmaf(w0, v0.y, a1);
        a0 = fmaf(w1, v1.x, a0); a1 = fmaf(w1, v1.y, a1);
        a0 = fmaf(w2, v2.x, a0); a1 = fmaf(w2, v2.y, a1);
        a0 = fmaf(w3, v3.x, a0); a1 = fmaf(w3, v3.y, a1);
    }
    for (; e < end; e++) {
        int2 e0 = __ldcs(&g_edges[e]);
        uint32_t r0 = __ldcg((const uint32_t*)&H9[(size_t)e0.x * CC + lane * 2]);
        float2 v0 = __half22float2(*(__half2*)&r0);
        float w0 = __int_as_float(e0.y);
        a0 = fmaf(w0, v0.x, a0); a1 = fmaf(w0, v0.y, a1);
    }
    {
        float p = a0 * wpx + a1 * wpy;
#pragma unroll
        for (int o = 16; o; o >>= 1) p += __shfl_xor_sync(0xffffffffu, p, o);
        float s = 1.f / (1.f + __expf(-p));
        ax = fmaf(s, a0, ax);
        ay = fmaf(s, a1, ay);
    }

    *(float2*)&out[(size_t)w * CC + lane * 2] = make_float2(ax, ay);
}

extern "C" void kernel_launch(void* const* d_in, const int* in_sizes, int n_in,
                              void* d_out, int out_size) {
    const float* x    = (const float*)d_in[0];
    const int*   esrc = (const int*)d_in[1];
    const int*   edst = (const int*)d_in[2];
    const float* ew   = (const float*)d_in[3];
    const int*   nidx = (const int*)d_in[4];
    const float* W1   = (const float*)d_in[5];
    const float* W2   = (const float*)d_in[6];
    const float* wp   = (const float*)d_in[7];

    int N  = in_sizes[0] / DD;
    int E  = in_sizes[1];
    int NI = in_sizes[4];

    __half* H0;
    cudaGetSymbolAddress((void**)&H0, g_H);

    cudaFuncSetAttribute(mlp_mma_kernel,
                         cudaFuncAttributeMaxDynamicSharedMemorySize, MLP_SMEM);

    // one-time resource init (resources only; captured work is identical each call)
    static cudaStream_t s_mlp = nullptr;
    static cudaEvent_t ev_fork = nullptr, ev_join = nullptr;
    if (s_mlp == nullptr) {
        cudaStreamCreateWithFlags(&s_mlp, cudaStreamNonBlocking);
        cudaEventCreateWithFlags(&ev_fork, cudaEventDisableTiming);
        cudaEventCreateWithFlags(&ev_join, cudaEventDisableTiming);
    }

    // fork: MLP on side stream, CSR build on main stream (independent dataflows)
    cudaEventRecord(ev_fork, 0);
    cudaStreamWaitEvent(s_mlp, ev_fork, 0);
    mlp_mma_kernel<<<(N + 255) / 256, 256, MLP_SMEM, s_mlp>>>(x, W1, W2, H0, N);
    cudaEventRecord(ev_join, s_mlp);

    // CSR-by-dst build on main stream
    zero_kernel<<<(N + 255) / 256, 256>>>(N);
    count_kernel<<<(E + 255) / 256, 256>>>(edst, E);
    scan_partial_kernel<<<SCAN_NB, 256>>>(N);
    scan_top_kernel<<<1, 256>>>(SCAN_NB, N);
    rowptr_kernel<<<SCAN_NB, 256>>>(N);
    fill_kernel<<<(E + 255) / 256, 256>>>(esrc, edst, ew, E);

    // join: hops need both CSR and H[0]
    cudaStreamWaitEvent(0, ev_join, 0);

    // 9 full propagation hops: H[k] -> H[k+1] (hop 10 is computed lazily)
    for (int k = 0; k < KHOPS - 1; k++)
        spmm_kernel<<<(N * 32 + 255) / 256, 256>>>(H0 + (size_t)k * NN * CC,
                                                   H0 + (size_t)(k + 1) * NN * CC, N);

    // lazy hop-10 + gating + gather for requested nodes only
    final_kernel<<<(NI * 32 + 255) / 256, 256>>>(nidx, wp, (float*)d_out, NI);
}

// round 15
// speedup vs baseline: 1.0431x; 1.0431x over previous
#include <cuda_runtime.h>
#include <cuda_bf16.h>
#include <cuda_fp16.h>
#include <cstdint>

#define NN 100000
#define EE 1600000
#define CC 64
#define DD 512
#define KHOPS 10

#define SCAN_B 512                      // elements per scan block
#define SCAN_NB ((NN + SCAN_B - 1) / SCAN_B)

// ---- device scratch ----
__device__ __half g_H[KHOPS * (size_t)NN * CC];  // hop features 0..9, fp16 (hop 10 lazy)
__device__ int   g_deg[NN];
__device__ int   g_rowptr[NN + 1];
__device__ int   g_cursor[NN];
__device__ int   g_part[SCAN_NB];
__device__ int2  g_edges[EE];       // .x = src, .y = float bits of weight

// ---------------- preprocessing: CSR by destination ----------------

__global__ void zero_kernel(int n) {
    int i = blockIdx.x * blockDim.x + threadIdx.x;
    if (i < n) g_deg[i] = 0;
}

__global__ void count_kernel(const int* __restrict__ dst, int e) {
    int i = blockIdx.x * blockDim.x + threadIdx.x;
    if (i < e) atomicAdd(&g_deg[dst[i]], 1);
}

__global__ void scan_partial_kernel(int n) {
    __shared__ int s[256];
    int b = blockIdx.x, t = threadIdx.x;
    int i0 = b * SCAN_B + t * 2;
    int v = 0;
    if (i0 < n)     v += g_deg[i0];
    if (i0 + 1 < n) v += g_deg[i0 + 1];
    s[t] = v;
    __syncthreads();
    for (int off = 128; off; off >>= 1) {
        if (t < off) s[t] += s[t + off];
        __syncthreads();
    }
    if (t == 0) g_part[b] = s[0];
}

__global__ void scan_top_kernel(int nb, int n) {
    __shared__ int s[256];
    int t = threadIdx.x;
    int v = (t < nb) ? g_part[t] : 0;
    s[t] = v;
    __syncthreads();
    for (int off = 1; off < 256; off <<= 1) {
        int add = (t >= off) ? s[t - off] : 0;
        __syncthreads();
        s[t] += add;
        __syncthreads();
    }
    if (t < nb) g_part[t] = s[t] - v;        // exclusive
    if (t == 255) g_rowptr[n] = s[255];      // total
}

__global__ void rowptr_kernel(int n) {
    __shared__ int s[256];
    int b = blockIdx.x, t = threadIdx.x;
    int i0 = b * SCAN_B + t * 2;
    int d0 = (i0 < n)     ? g_deg[i0]     : 0;
    int d1 = (i0 + 1 < n) ? g_deg[i0 + 1] : 0;
    int pair = d0 + d1;
    s[t] = pair;
    __syncthreads();
    for (int off = 1; off < 256; off <<= 1) {
        int add = (t >= off) ? s[t - off] : 0;
        __syncthreads();
        s[t] += add;
        __syncthreads();
    }
    int base = g_part[b] + s[t] - pair;      // exclusive prefix for i0
    if (i0 < n)     { g_rowptr[i0] = base;          g_cursor[i0] = base; }
    if (i0 + 1 < n) { g_rowptr[i0 + 1] = base + d0; g_cursor[i0 + 1] = base + d0; }
}

__global__ void fill_kernel(const int* __restrict__ src, const int* __restrict__ dst,
                            const float* __restrict__ w, int e) {
    int i = blockIdx.x * blockDim.x + threadIdx.x;
    if (i < e) {
        int pos = atomicAdd(&g_cursor[dst[i]], 1);
        g_edges[pos] = make_int2(src[i], __float_as_int(w[i]));
    }
}

// ---------------- tensor-core MLP: h = relu(relu(x@W1)@W2) ----------------
// bf16 double-split (hi+lo), 3x mma.sync.m16n8k16 => ~fp32 precision.
// 256-row block tile (best-measured config, R11).
#define MLP_SMEM 83968
#define S1_STRIDE 40
#define S2_STRIDE 72

__device__ __forceinline__ void mma_bf16(float* c, uint32_t a0, uint32_t a1,
                                         uint32_t a2, uint32_t a3,
                                         uint32_t b0, uint32_t b1) {
    asm volatile(
        "mma.sync.aligned.m16n8k16.row.col.f32.bf16.bf16.f32 "
        "{%0,%1,%2,%3}, {%4,%5,%6,%7}, {%8,%9}, {%0,%1,%2,%3};\n"
        : "+f"(c[0]), "+f"(c[1]), "+f"(c[2]), "+f"(c[3])
        : "r"(a0), "r"(a1), "r"(a2), "r"(a3), "r"(b0), "r"(b1));
}

__device__ __forceinline__ void split2(float x, float y, uint32_t& hi, uint32_t& lo) {
    __nv_bfloat162 h2 = __floats2bfloat162_rn(x, y);
    float rx = x - __bfloat162float(h2.x);
    float ry = y - __bfloat162float(h2.y);
    __nv_bfloat162 l2 = __floats2bfloat162_rn(rx, ry);
    hi = *(uint32_t*)&h2;
    lo = *(uint32_t*)&l2;
}

__global__ __launch_bounds__(256) void mlp_mma_kernel(const float* __restrict__ x,
                                                      const float* __restrict__ W1,
                                                      const float* __restrict__ W2,
                                                      __half* __restrict__ h_out,
                                                      int n) {
    extern __shared__ char sm[];
    __nv_bfloat16* uHi = (__nv_bfloat16*)sm;
    __nv_bfloat16* uLo = (__nv_bfloat16*)(sm + 36864);
    __nv_bfloat16* bHi = (__nv_bfloat16*)(sm + 73728);
    __nv_bfloat16* bLo = (__nv_bfloat16*)(sm + 78848);

    int tid  = threadIdx.x;
    int lane = tid & 31;
    int warp = tid >> 5;
    int g  = lane >> 2;
    int tg = lane & 3;
    int row0 = blockIdx.x * 256;
    int warpRow = warp * 32;

    float acc[2][8][4];
#pragma unroll
    for (int rg = 0; rg < 2; rg++)
#pragma unroll
        for (int nt = 0; nt < 8; nt++)
#pragma unroll
            for (int q = 0; q < 4; q++) acc[rg][nt][q] = 0.f;

    // ---- stage 1: h1 = relu(x @ W1), K = 512 in 16 chunks of 32 ----
    for (int kc = 0; kc < 16; kc++) {
        int k0 = kc * 32;
        __syncthreads();
        for (int p = tid; p < 2048; p += 256) {
            int r = p >> 3, c4 = p & 7;
            float4 v = make_float4(0.f, 0.f, 0.f, 0.f);
            if (row0 + r < n)
                v = __ldcs((const float4*)&x[(size_t)(row0 + r) * DD + k0 + c4 * 4]);
            uint32_t h0, l0, h1v, l1v;
            split2(v.x, v.y, h0, l0);
            split2(v.z, v.w, h1v, l1v);
            int base = r * S1_STRIDE + c4 * 4;
            *(uint32_t*)&uHi[base]     = h0;
            *(uint32_t*)&uHi[base + 2] = h1v;
            *(uint32_t*)&uLo[base]     = l0;
            *(uint32_t*)&uLo[base + 2] = l1v;
        }
        for (int p = tid; p < 512; p += 256) {
            int k = p >> 4, n4 = p & 15;
            float4 v = *(const float4*)&W1[(size_t)(k0 + k) * CC + n4 * 4];
            float vv[4] = {v.x, v.y, v.z, v.w};
#pragma unroll
            for (int j = 0; j < 4; j++) {
                int nn = n4 * 4 + j;
                __nv_bfloat16 h = __float2bfloat16(vv[j]);
                __nv_bfloat16 l = __float2bfloat16(vv[j] - __bfloat162float(h));
                bHi[nn * S1_STRIDE + k] = h;
                bLo[nn * S1_STRIDE + k] = l;
            }
        }
        __syncthreads();

#pragma unroll
        for (int ks = 0; ks < 2; ks++) {
            int kb = ks * 16;
            uint32_t aHi[2][4], aLo[2][4];
#pragma unroll
            for (int rg = 0; rg < 2; rg++) {
                int r = warpRow + rg * 16 + g;
                int i0 = r * S1_STRIDE + kb + tg * 2;
                int i1 = (r + 8) * S1_STRIDE + kb + tg * 2;
                aHi[rg][0] = *(uint32_t*)&uHi[i0];
                aHi[rg][1] = *(uint32_t*)&uHi[i1];
                aHi[rg][2] = *(uint32_t*)&uHi[i0 + 8];
                aHi[rg][3] = *(uint32_t*)&uHi[i1 + 8];
                aLo[rg][0] = *(uint32_t*)&uLo[i0];
                aLo[rg][1] = *(uint32_t*)&uLo[i1];
                aLo[rg][2] = *(uint32_t*)&uLo[i0 + 8];
                aLo[rg][3] = *(uint32_t*)&uLo[i1 + 8];
            }
#pragma unroll
            for (int nt = 0; nt < 8; nt++) {
                int bi = (nt * 8 + g) * S1_STRIDE + kb + tg * 2;
                uint32_t b0h = *(uint32_t*)&bHi[bi];
                uint32_t b1h = *(uint32_t*)&bHi[bi + 8];
                uint32_t b0l = *(uint32_t*)&bLo[bi];
                uint32_t b1l = *(uint32_t*)&bLo[bi + 8];
#pragma unroll
                for (int rg = 0; rg < 2; rg++) {
                    mma_bf16(acc[rg][nt], aHi[rg][0], aHi[rg][1], aHi[rg][2], aHi[rg][3], b0h, b1h);
                    mma_bf16(acc[rg][nt], aHi[rg][0], aHi[rg][1], aHi[rg][2], aHi[rg][3], b0l, b1l);
                    mma_bf16(acc[rg][nt], aLo[rg][0], aLo[rg][1], aLo[rg][2], aLo[rg][3], b0h, b1h);
                }
            }
        }
    }

    // ---- relu(h1) -> smem bf16 hi/lo, reset acc ----
    __syncthreads();
#pragma unroll
    for (int rg = 0; rg < 2; rg++) {
        int r1 = warpRow + rg * 16 + g;
        int r2 = r1 + 8;
#pragma unroll
        for (int nt = 0; nt < 8; nt++) {
            int col = nt * 8 + tg * 2;
            float v0 = fmaxf(acc[rg][nt][0], 0.f);
            float v1 = fmaxf(acc[rg][nt][1], 0.f);
            float v2 = fmaxf(acc[rg][nt][2], 0.f);
            float v3 = fmaxf(acc[rg][nt][3], 0.f);
            uint32_t h, l;
            split2(v0, v1, h, l);
            *(uint32_t*)&uHi[r1 * S2_STRIDE + col] = h;
            *(uint32_t*)&uLo[r1 * S2_STRIDE + col] = l;
            split2(v2, v3, h, l);
            *(uint32_t*)&uHi[r2 * S2_STRIDE + col] = h;
            *(uint32_t*)&uLo[r2 * S2_STRIDE + col] = l;
#pragma unroll
            for (int q = 0; q < 4; q++) acc[rg][nt][q] = 0.f;
        }
    }
    __syncthreads();

    // ---- stage 2: h = relu(h1 @ W2), K = 64 ----
    for (int c2 = 0; c2 < 2; c2++) {
        if (c2) __syncthreads();
        for (int p = tid; p < 512; p += 256) {
            int k = p >> 4, n4 = p & 15;
            float4 v = *(const float4*)&W2[(size_t)(c2 * 32 + k) * CC + n4 * 4];
            float vv[4] = {v.x, v.y, v.z, v.w};
#pragma unroll
            for (int j = 0; j < 4; j++) {
                int nn = n4 * 4 + j;
                __nv_bfloat16 h = __float2bfloat16(vv[j]);
                __nv_bfloat16 l = __float2bfloat16(vv[j] - __bfloat162float(h));
                bHi[nn * S1_STRIDE + k] = h;
                bLo[nn * S1_STRIDE + k] = l;
            }
        }
        __syncthreads();

#pragma unroll
        for (int ks = 0; ks < 2; ks++) {
            int kb = c2 * 32 + ks * 16;
            int kbb = ks * 16;
            uint32_t aHi[2][4], aLo[2][4];
#pragma unroll
            for (int rg = 0; rg < 2; rg++) {
                int r = warpRow + rg * 16 + g;
                int i0 = r * S2_STRIDE + kb + tg * 2;
                int i1 = (r + 8) * S2_STRIDE + kb + tg * 2;
                aHi[rg][0] = *(uint32_t*)&uHi[i0];
                aHi[rg][1] = *(uint32_t*)&uHi[i1];
                aHi[rg][2] = *(uint32_t*)&uHi[i0 + 8];
                aHi[rg][3] = *(uint32_t*)&uHi[i1 + 8];
                aLo[rg][0] = *(uint32_t*)&uLo[i0];
                aLo[rg][1] = *(uint32_t*)&uLo[i1];
                aLo[rg][2] = *(uint32_t*)&uLo[i0 + 8];
                aLo[rg][3] = *(uint32_t*)&uLo[i1 + 8];
            }
#pragma unroll
            for (int nt = 0; nt < 8; nt++) {
                int bi = (nt * 8 + g) * S1_STRIDE + kbb + tg * 2;
                uint32_t b0h = *(uint32_t*)&bHi[bi];
                uint32_t b1h = *(uint32_t*)&bHi[bi + 8];
                uint32_t b0l = *(uint32_t*)&bLo[bi];
                uint32_t b1l = *(uint32_t*)&bLo[bi + 8];
#pragma unroll
                for (int rg = 0; rg < 2; rg++) {
                    mma_bf16(acc[rg][nt], aHi[rg][0], aHi[rg][1], aHi[rg][2], aHi[rg][3], b0h, b1h);
                    mma_bf16(acc[rg][nt], aHi[rg][0], aHi[rg][1], aHi[rg][2], aHi[rg][3], b0l, b1l);
                    mma_bf16(acc[rg][nt], aLo[rg][0], aLo[rg][1], aLo[rg][2], aLo[rg][3], b0h, b1h);
                }
            }
        }
    }

    // ---- relu + store to h_out (fp16) ----
#pragma unroll
    for (int rg = 0; rg < 2; rg++) {
        int r1 = row0 + warpRow + rg * 16 + g;
        int r2 = r1 + 8;
#pragma unroll
        for (int nt = 0; nt < 8; nt++) {
            int col = nt * 8 + tg * 2;
            if (r1 < n)
                *(__half2*)&h_out[(size_t)r1 * CC + col] =
                    __floats2half2_rn(fmaxf(acc[rg][nt][0], 0.f), fmaxf(acc[rg][nt][1], 0.f));
            if (r2 < n)
                *(__half2*)&h_out[(size_t)r2 * CC + col] =
                    __floats2half2_rn(fmaxf(acc[rg][nt][2], 0.f), fmaxf(acc[rg][nt][3], 0.f));
        }
    }
}

// ---------------- SpMM hop: warp per dst row, fp16, 4 edges per LDG.128 ----------------
// Plain cached loads (R11 best-measured config: L1 reuse on gathers is real).
__device__ __forceinline__ void accum8(float* a, uint4 f, float ww) {
    float2 p0 = __half22float2(*(__half2*)&f.x);
    float2 p1 = __half22float2(*(__half2*)&f.y);
    float2 p2 = __half22float2(*(__half2*)&f.z);
    float2 p3 = __half22float2(*(__half2*)&f.w);
    a[0] = fmaf(ww, p0.x, a[0]); a[1] = fmaf(ww, p0.y, a[1]);
    a[2] = fmaf(ww, p1.x, a[2]); a[3] = fmaf(ww, p1.y, a[3]);
    a[4] = fmaf(ww, p2.x, a[4]); a[5] = fmaf(ww, p2.y, a[5]);
    a[6] = fmaf(ww, p3.x, a[6]); a[7] = fmaf(ww, p3.y, a[7]);
}

__global__ __launch_bounds__(256) void spmm_kernel(const __half* __restrict__ cur,
                                                   __half* __restrict__ nxt, int n) {
    int w = (blockIdx.x * blockDim.x + threadIdx.x) >> 5;
    int lane = threadIdx.x & 31;
    if (w >= n) return;
    int q  = lane >> 3;
    int c8 = (lane & 7) * 8;

    int beg = g_rowptr[w];
    int end = g_rowptr[w + 1];
    float a[8];
#pragma unroll
    for (int i = 0; i < 8; i++) a[i] = 0.f;

    int e = beg;
    for (; e + 7 < end; e += 8) {
        int2 ed0 = g_edges[e + 2 * q];
        int2 ed1 = g_edges[e + 2 * q + 1];
        uint4 f0 = *(const uint4*)&cur[(size_t)ed0.x * CC + c8];
        uint4 f1 = *(const uint4*)&cur[(size_t)ed1.x * CC + c8];
        accum8(a, f0, __int_as_float(ed0.y));
        accum8(a, f1, __int_as_float(ed1.y));
    }
    for (; e < end; e += 4) {
        int myE = e + q;
        if (myE < end) {
            int2 ed = g_edges[myE];
            uint4 f = *(const uint4*)&cur[(size_t)ed.x * CC + c8];
            accum8(a, f, __int_as_float(ed.y));
        }
    }

#pragma unroll
    for (int i = 0; i < 8; i++) {
        a[i] += __shfl_xor_sync(0xffffffffu, a[i], 8);
        a[i] += __shfl_xor_sync(0xffffffffu, a[i], 16);
    }

    if (q == 0) {
        uint4 st;
        *(__half2*)&st.x = __floats2half2_rn(a[0], a[1]);
        *(__half2*)&st.y = __floats2half2_rn(a[2], a[3]);
        *(__half2*)&st.z = __floats2half2_rn(a[4], a[5]);
        *(__half2*)&st.w = __floats2half2_rn(a[6], a[7]);
        *(uint4*)&nxt[(size_t)w * CC + c8] = st;
    }
}

// ---------------- final: lazy hop-10 + gating + gather, requested nodes only ----------------
__global__ void final_kernel(const int* __restrict__ idx,
                             const float* __restrict__ wp,
                             float* __restrict__ out, int ni) {
    int w = (blockIdx.x * blockDim.x + threadIdx.x) >> 5;
    int lane = threadIdx.x & 31;
    if (w >= ni) return;
    int nd = idx[w];
    float wpx = __ldg(&wp[lane * 2]);
    float wpy = __ldg(&wp[lane * 2 + 1]);
    float ax = 0.f, ay = 0.f;

    // hops 0..9 from storage (fp16)
#pragma unroll
    for (int k = 0; k < KHOPS; k++) {
        __half2 vh = *(const __half2*)&g_H[(size_t)k * NN * CC + (size_t)nd * CC + lane * 2];
        float2 v = __half22float2(vh);
        float p = v.x * wpx + v.y * wpy;
#pragma unroll
        for (int o = 16; o; o >>= 1) p += __shfl_xor_sync(0xffffffffu, p, o);
        float s = 1.f / (1.f + __expf(-p));
        ax = fmaf(s, v.x, ax);
        ay = fmaf(s, v.y, ay);
    }

    // hop 10 computed lazily from H[9] (fp16 in, fp32 accum)
    const __half* __restrict__ H9 = g_H + (size_t)(KHOPS - 1) * NN * CC;
    int beg = g_rowptr[nd];
    int end = g_rowptr[nd + 1];
    float a0 = 0.f, a1 = 0.f;
    int e = beg;
    for (; e + 3 < end; e += 4) {
        int2 e0 = g_edges[e];
        int2 e1 = g_edges[e + 1];
        int2 e2 = g_edges[e + 2];
        int2 e3 = g_edges[e + 3];
        float2 v0 = __half22float2(*(const __half2*)&H9[(size_t)e0.x * CC + lane * 2]);
        float2 v1 = __half22float2(*(const __half2*)&H9[(size_t)e1.x * CC + lane * 2]);
        float2 v2 = __half22float2(*(const __half2*)&H9[(size_t)e2.x * CC + lane * 2]);
        float2 v3 = __half22float2(*(const __half2*)&H9[(size_t)e3.x * CC + lane * 2]);
        float w0 = __int_as_float(e0.y);
        float w1 = __int_as_float(e1.y);
        float w2 = __int_as_float(e2.y);
        float w3 = __int_as_float(e3.y);
        a0 = fmaf(w0, v0.x, a0); a1 = fmaf(w0, v0.y, a1);
        a0 = fmaf(w1, v1.x, a0); a1 = fmaf(w1, v1.y, a1);
        a0 = fmaf(w2, v2.x, a0); a1 = fmaf(w2, v2.y, a1);
        a0 = fmaf(w3, v3.x, a0); a1 = fmaf(w3, v3.y, a1);
    }
    for (; e < end; e++) {
        int2 e0 = g_edges[e];
        float2 v0 = __half22float2(*(const __half2*)&H9[(size_t)e0.x * CC + lane * 2]);
        float w0 = __int_as_float(e0.y);
        a0 = fmaf(w0, v0.x, a0); a1 = fmaf(w0, v0.y, a1);
    }
    {
        float p = a0 * wpx + a1 * wpy;
#pragma unroll
        for (int o = 16; o; o >>= 1) p += __shfl_xor_sync(0xffffffffu, p, o);
        float s = 1.f / (1.f + __expf(-p));
        ax = fmaf(s, a0, ax);
        ay = fmaf(s, a1, ay);
    }

    *(float2*)&out[(size_t)w * CC + lane * 2] = make_float2(ax, ay);
}

extern "C" void kernel_launch(void* const* d_in, const int* in_sizes, int n_in,
                              void* d_out, int out_size) {
    const float* x    = (const float*)d_in[0];
    const int*   esrc = (const int*)d_in[1];
    const int*   edst = (const int*)d_in[2];
    const float* ew   = (const float*)d_in[3];
    const int*   nidx = (const int*)d_in[4];
    const float* W1   = (const float*)d_in[5];
    const float* W2   = (const float*)d_in[6];
    const float* wp   = (const float*)d_in[7];

    int N  = in_sizes[0] / DD;
    int E  = in_sizes[1];
    int NI = in_sizes[4];

    __half* H0;
    cudaGetSymbolAddress((void**)&H0, g_H);

    cudaFuncSetAttribute(mlp_mma_kernel,
                         cudaFuncAttributeMaxDynamicSharedMemorySize, MLP_SMEM);

    // one-time resource init (resources only; captured work is identical each call)
    static cudaStream_t s_mlp = nullptr;
    static cudaEvent_t ev_fork = nullptr, ev_join = nullptr;
    if (s_mlp == nullptr) {
        cudaStreamCreateWithFlags(&s_mlp, cudaStreamNonBlocking);
        cudaEventCreateWithFlags(&ev_fork, cudaEventDisableTiming);
        cudaEventCreateWithFlags(&ev_join, cudaEventDisableTiming);
    }

    // fork: MLP on side stream, CSR build on main stream (independent dataflows)
    cudaEventRecord(ev_fork, 0);
    cudaStreamWaitEvent(s_mlp, ev_fork, 0);
    mlp_mma_kernel<<<(N + 255) / 256, 256, MLP_SMEM, s_mlp>>>(x, W1, W2, H0, N);
    cudaEventRecord(ev_join, s_mlp);

    // CSR-by-dst build on main stream
    zero_kernel<<<(N + 255) / 256, 256>>>(N);
    count_kernel<<<(E + 255) / 256, 256>>>(edst, E);
    scan_partial_kernel<<<SCAN_NB, 256>>>(N);
    scan_top_kernel<<<1, 256>>>(SCAN_NB, N);
    rowptr_kernel<<<SCAN_NB, 256>>>(N);
    fill_kernel<<<(E + 255) / 256, 256>>>(esrc, edst, ew, E);

    // join: hops need both CSR and H[0]
    cudaStreamWaitEvent(0, ev_join, 0);

    // 9 full propagation hops: H[k] -> H[k+1] (hop 10 is computed lazily)
    for (int k = 0; k < KHOPS - 1; k++)
        spmm_kernel<<<(N * 32 + 255) / 256, 256>>>(H0 + (size_t)k * NN * CC,
                                                   H0 + (size_t)(k + 1) * NN * CC, N);

    // lazy hop-10 + gating + gather for requested nodes only
    final_kernel<<<(NI * 32 + 255) / 256, 256>>>(nidx, wp, (float*)d_out, NI);
}

// round 16
// speedup vs baseline: 1.1918x; 1.1425x over previous
#include <cuda_runtime.h>
#include <cuda_bf16.h>
#include <cuda_fp16.h>
#include <cstdint>

#define NN 100000
#define EE 1600000
#define CC 64
#define DD 512
#define KHOPS 10

#define SCAN_B 512                      // elements per scan block
#define SCAN_NB ((NN + SCAN_B - 1) / SCAN_B)

// ---- device scratch ----
__device__ __half g_H[KHOPS * (size_t)NN * CC];  // hop features 0..9, fp16 (hop 10 lazy)
__device__ int   g_deg[NN];
__device__ int   g_rowptr[NN + 1];
__device__ int   g_cursor[NN];
__device__ int   g_part[SCAN_NB];
__device__ int2  g_edges[EE];       // .x = src, .y = float bits of weight

// ---------------- preprocessing: CSR by destination ----------------

__global__ void zero_kernel(int n) {
    int i = blockIdx.x * blockDim.x + threadIdx.x;
    if (i < n) g_deg[i] = 0;
}

__global__ void count_kernel(const int* __restrict__ dst, int e) {
    int i = blockIdx.x * blockDim.x + threadIdx.x;
    if (i < e) atomicAdd(&g_deg[dst[i]], 1);
}

__global__ void scan_partial_kernel(int n) {
    __shared__ int s[256];
    int b = blockIdx.x, t = threadIdx.x;
    int i0 = b * SCAN_B + t * 2;
    int v = 0;
    if (i0 < n)     v += g_deg[i0];
    if (i0 + 1 < n) v += g_deg[i0 + 1];
    s[t] = v;
    __syncthreads();
    for (int off = 128; off; off >>= 1) {
        if (t < off) s[t] += s[t + off];
        __syncthreads();
    }
    if (t == 0) g_part[b] = s[0];
}

__global__ void scan_top_kernel(int nb, int n) {
    __shared__ int s[256];
    int t = threadIdx.x;
    int v = (t < nb) ? g_part[t] : 0;
    s[t] = v;
    __syncthreads();
    for (int off = 1; off < 256; off <<= 1) {
        int add = (t >= off) ? s[t - off] : 0;
        __syncthreads();
        s[t] += add;
        __syncthreads();
    }
    if (t < nb) g_part[t] = s[t] - v;        // exclusive
    if (t == 255) g_rowptr[n] = s[255];      // total
}

__global__ void rowptr_kernel(int n) {
    __shared__ int s[256];
    int b = blockIdx.x, t = threadIdx.x;
    int i0 = b * SCAN_B + t * 2;
    int d0 = (i0 < n)     ? g_deg[i0]     : 0;
    int d1 = (i0 + 1 < n) ? g_deg[i0 + 1] : 0;
    int pair = d0 + d1;
    s[t] = pair;
    __syncthreads();
    for (int off = 1; off < 256; off <<= 1) {
        int add = (t >= off) ? s[t - off] : 0;
        __syncthreads();
        s[t] += add;
        __syncthreads();
    }
    int base = g_part[b] + s[t] - pair;      // exclusive prefix for i0
    if (i0 < n)     { g_rowptr[i0] = base;          g_cursor[i0] = base; }
    if (i0 + 1 < n) { g_rowptr[i0 + 1] = base + d0; g_cursor[i0 + 1] = base + d0; }
}

__global__ void fill_kernel(const int* __restrict__ src, const int* __restrict__ dst,
                            const float* __restrict__ w, int e) {
    int i = blockIdx.x * blockDim.x + threadIdx.x;
    if (i < e) {
        int pos = atomicAdd(&g_cursor[dst[i]], 1);
        g_edges[pos] = make_int2(src[i], __float_as_int(w[i]));
    }
}

// ---------------- tensor-core MLP: h = relu(relu(x@W1)@W2) ----------------
// bf16 double-split (hi+lo), 3x mma.sync.m16n8k16 => ~fp32 precision.
// 256-row block tile. Stage-1 x loads pipelined via cp.async into smem staging
// placed in the unused tails of the stage-1 split-buffer regions (smem total unchanged).
#define MLP_SMEM 83968
#define S1_STRIDE 40
#define S2_STRIDE 72
// stage-1 split region use: 256*40*2 = 20480 of 36864 bytes -> 16384-byte gap per region
#define STAG0_OFF 20480u
#define STAG1_OFF (36864u + 20480u)

__device__ __forceinline__ void mma_bf16(float* c, uint32_t a0, uint32_t a1,
                                         uint32_t a2, uint32_t a3,
                                         uint32_t b0, uint32_t b1) {
    asm volatile(
        "mma.sync.aligned.m16n8k16.row.col.f32.bf16.bf16.f32 "
        "{%0,%1,%2,%3}, {%4,%5,%6,%7}, {%8,%9}, {%0,%1,%2,%3};\n"
        : "+f"(c[0]), "+f"(c[1]), "+f"(c[2]), "+f"(c[3])
        : "r"(a0), "r"(a1), "r"(a2), "r"(a3), "r"(b0), "r"(b1));
}

__device__ __forceinline__ void split2(float x, float y, uint32_t& hi, uint32_t& lo) {
    __nv_bfloat162 h2 = __floats2bfloat162_rn(x, y);
    float rx = x - __bfloat162float(h2.x);
    float ry = y - __bfloat162float(h2.y);
    __nv_bfloat162 l2 = __floats2bfloat162_rn(rx, ry);
    hi = *(uint32_t*)&h2;
    lo = *(uint32_t*)&l2;
}

// staging address for (row r in [0,256), c4 in [0,8)): 128 B per row, split across two gaps
__device__ __forceinline__ uint32_t stag_off(int r, int c4) {
    uint32_t base = (r < 128) ? STAG0_OFF : STAG1_OFF;
    return base + (uint32_t)(r & 127) * 128u + (uint32_t)c4 * 16u;
}

__global__ __launch_bounds__(256) void mlp_mma_kernel(const float* __restrict__ x,
                                                      const float* __restrict__ W1,
                                                      const float* __restrict__ W2,
                                                      __half* __restrict__ h_out,
                                                      int n) {
    extern __shared__ char sm[];
    __nv_bfloat16* uHi = (__nv_bfloat16*)sm;
    __nv_bfloat16* uLo = (__nv_bfloat16*)(sm + 36864);
    __nv_bfloat16* bHi = (__nv_bfloat16*)(sm + 73728);
    __nv_bfloat16* bLo = (__nv_bfloat16*)(sm + 78848);

    uint32_t smBase;
    asm("{ .reg .u64 t; cvta.to.shared.u64 t, %1; cvt.u32.u64 %0, t; }"
        : "=r"(smBase) : "l"(sm));

    int tid  = threadIdx.x;
    int lane = tid & 31;
    int warp = tid >> 5;
    int g  = lane >> 2;
    int tg = lane & 3;
    int row0 = blockIdx.x * 256;
    int warpRow = warp * 32;

    float acc[2][8][4];
#pragma unroll
    for (int rg = 0; rg < 2; rg++)
#pragma unroll
        for (int nt = 0; nt < 8; nt++)
#pragma unroll
            for (int q = 0; q < 4; q++) acc[rg][nt][q] = 0.f;

    // issue cp.async for one x chunk (32 KB) into staging; OOB rows clamped (zeroed at convert)
    auto issue_chunk = [&](int k0) {
#pragma unroll
        for (int i = 0; i < 8; i++) {
            int p = tid + i * 256;
            int r = p >> 3, c4 = p & 7;
            int rr = row0 + r;
            if (rr >= n) rr = 0;                       // clamp to valid address
            const float* src = &x[(size_t)rr * DD + k0 + c4 * 4];
            uint32_t dst = smBase + stag_off(r, c4);
            asm volatile("cp.async.cg.shared.global [%0], [%1], 16;"
                         :: "r"(dst), "l"(src));
        }
        asm volatile("cp.async.commit_group;");
    };

    // ---- stage 1: h1 = relu(x @ W1), K = 512 in 16 chunks of 32, cp.async pipelined ----
    issue_chunk(0);
    for (int kc = 0; kc < 16; kc++) {
        int k0 = kc * 32;
        asm volatile("cp.async.wait_group 0;");
        __syncthreads();                               // staging holds chunk kc

        // convert staging -> bf16 hi/lo split buffers
        for (int p = tid; p < 2048; p += 256) {
            int r = p >> 3, c4 = p & 7;
            float4 v = *(const float4*)(sm + stag_off(r, c4));
            if (row0 + r >= n) v = make_float4(0.f, 0.f, 0.f, 0.f);
            uint32_t h0, l0, h1v, l1v;
            split2(v.x, v.y, h0, l0);
            split2(v.z, v.w, h1v, l1v);
            int base = r * S1_STRIDE + c4 * 4;
            *(uint32_t*)&uHi[base]     = h0;
            *(uint32_t*)&uHi[base + 2] = h1v;
            *(uint32_t*)&uLo[base]     = l0;
            *(uint32_t*)&uLo[base + 2] = l1v;
        }
        for (int p = tid; p < 512; p += 256) {
            int k = p >> 4, n4 = p & 15;
            float4 v = *(const float4*)&W1[(size_t)(k0 + k) * CC + n4 * 4];
            float vv[4] = {v.x, v.y, v.z, v.w};
#pragma unroll
            for (int j = 0; j < 4; j++) {
                int nn = n4 * 4 + j;
                __nv_bfloat16 h = __float2bfloat16(vv[j]);
                __nv_bfloat16 l = __float2bfloat16(vv[j] - __bfloat162float(h));
                bHi[nn * S1_STRIDE + k] = h;
                bLo[nn * S1_STRIDE + k] = l;
            }
        }
        __syncthreads();                               // staging free to overwrite

        if (kc < 15) issue_chunk(k0 + 32);             // flies during the MMAs below

#pragma unroll
        for (int ks = 0; ks < 2; ks++) {
            int kb = ks * 16;
            uint32_t aHi[2][4], aLo[2][4];
#pragma unroll
            for (int rg = 0; rg < 2; rg++) {
                int r = warpRow + rg * 16 + g;
                int i0 = r * S1_STRIDE + kb + tg * 2;
                int i1 = (r + 8) * S1_STRIDE + kb + tg * 2;
                aHi[rg][0] = *(uint32_t*)&uHi[i0];
                aHi[rg][1] = *(uint32_t*)&uHi[i1];
                aHi[rg][2] = *(uint32_t*)&uHi[i0 + 8];
                aHi[rg][3] = *(uint32_t*)&uHi[i1 + 8];
                aLo[rg][0] = *(uint32_t*)&uLo[i0];
                aLo[rg][1] = *(uint32_t*)&uLo[i1];
                aLo[rg][2] = *(uint32_t*)&uLo[i0 + 8];
                aLo[rg][3] = *(uint32_t*)&uLo[i1 + 8];
            }
#pragma unroll
            for (int nt = 0; nt < 8; nt++) {
                int bi = (nt * 8 + g) * S1_STRIDE + kb + tg * 2;
                uint32_t b0h = *(uint32_t*)&bHi[bi];
                uint32_t b1h = *(uint32_t*)&bHi[bi + 8];
                uint32_t b0l = *(uint32_t*)&bLo[bi];
                uint32_t b1l = *(uint32_t*)&bLo[bi + 8];
#pragma unroll
                for (int rg = 0; rg < 2; rg++) {
                    mma_bf16(acc[rg][nt], aHi[rg][0], aHi[rg][1], aHi[rg][2], aHi[rg][3], b0h, b1h);
                    mma_bf16(acc[rg][nt], aHi[rg][0], aHi[rg][1], aHi[rg][2], aHi[rg][3], b0l, b1l);
                    mma_bf16(acc[rg][nt], aLo[rg][0], aLo[rg][1], aLo[rg][2], aLo[rg][3], b0h, b1h);
                }
            }
        }
    }

    // ---- relu(h1) -> smem bf16 hi/lo, reset acc ----
    __syncthreads();
#pragma unroll
    for (int rg = 0; rg < 2; rg++) {
        int r1 = warpRow + rg * 16 + g;
        int r2 = r1 + 8;
#pragma unroll
        for (int nt = 0; nt < 8; nt++) {
            int col = nt * 8 + tg * 2;
            float v0 = fmaxf(acc[rg][nt][0], 0.f);
            float v1 = fmaxf(acc[rg][nt][1], 0.f);
            float v2 = fmaxf(acc[rg][nt][2], 0.f);
            float v3 = fmaxf(acc[rg][nt][3], 0.f);
            uint32_t h, l;
            split2(v0, v1, h, l);
            *(uint32_t*)&uHi[r1 * S2_STRIDE + col] = h;
            *(uint32_t*)&uLo[r1 * S2_STRIDE + col] = l;
            split2(v2, v3, h, l);
            *(uint32_t*)&uHi[r2 * S2_STRIDE + col] = h;
            *(uint32_t*)&uLo[r2 * S2_STRIDE + col] = l;
#pragma unroll
            for (int q = 0; q < 4; q++) acc[rg][nt][q] = 0.f;
        }
    }
    __syncthreads();

    // ---- stage 2: h = relu(h1 @ W2), K = 64 ----
    for (int c2 = 0; c2 < 2; c2++) {
        if (c2) __syncthreads();
        for (int p = tid; p < 512; p += 256) {
            int k = p >> 4, n4 = p & 15;
            float4 v = *(const float4*)&W2[(size_t)(c2 * 32 + k) * CC + n4 * 4];
            float vv[4] = {v.x, v.y, v.z, v.w};
#pragma unroll
            for (int j = 0; j < 4; j++) {
                int nn = n4 * 4 + j;
                __nv_bfloat16 h = __float2bfloat16(vv[j]);
                __nv_bfloat16 l = __float2bfloat16(vv[j] - __bfloat162float(h));
                bHi[nn * S1_STRIDE + k] = h;
                bLo[nn * S1_STRIDE + k] = l;
            }
        }
        __syncthreads();

#pragma unroll
        for (int ks = 0; ks < 2; ks++) {
            int kb = c2 * 32 + ks * 16;
            int kbb = ks * 16;
            uint32_t aHi[2][4], aLo[2][4];
#pragma unroll
            for (int rg = 0; rg < 2; rg++) {
                int r = warpRow + rg * 16 + g;
                int i0 = r * S2_STRIDE + kb + tg * 2;
                int i1 = (r + 8) * S2_STRIDE + kb + tg * 2;
                aHi[rg][0] = *(uint32_t*)&uHi[i0];
                aHi[rg][1] = *(uint32_t*)&uHi[i1];
                aHi[rg][2] = *(uint32_t*)&uHi[i0 + 8];
                aHi[rg][3] = *(uint32_t*)&uHi[i1 + 8];
                aLo[rg][0] = *(uint32_t*)&uLo[i0];
                aLo[rg][1] = *(uint32_t*)&uLo[i1];
                aLo[rg][2] = *(uint32_t*)&uLo[i0 + 8];
                aLo[rg][3] = *(uint32_t*)&uLo[i1 + 8];
            }
#pragma unroll
            for (int nt = 0; nt < 8; nt++) {
                int bi = (nt * 8 + g) * S1_STRIDE + kbb + tg * 2;
                uint32_t b0h = *(uint32_t*)&bHi[bi];
                uint32_t b1h = *(uint32_t*)&bHi[bi + 8];
                uint32_t b0l = *(uint32_t*)&bLo[bi];
                uint32_t b1l = *(uint32_t*)&bLo[bi + 8];
#pragma unroll
                for (int rg = 0; rg < 2; rg++) {
                    mma_bf16(acc[rg][nt], aHi[rg][0], aHi[rg][1], aHi[rg][2], aHi[rg][3], b0h, b1h);
                    mma_bf16(acc[rg][nt], aHi[rg][0], aHi[rg][1], aHi[rg][2], aHi[rg][3], b0l, b1l);
                    mma_bf16(acc[rg][nt], aLo[rg][0], aLo[rg][1], aLo[rg][2], aLo[rg][3], b0h, b1h);
                }
            }
        }
    }

    // ---- relu + store to h_out (fp16) ----
#pragma unroll
    for (int rg = 0; rg < 2; rg++) {
        int r1 = row0 + warpRow + rg * 16 + g;
        int r2 = r1 + 8;
#pragma unroll
        for (int nt = 0; nt < 8; nt++) {
            int col = nt * 8 + tg * 2;
            if (r1 < n)
                *(__half2*)&h_out[(size_t)r1 * CC + col] =
                    __floats2half2_rn(fmaxf(acc[rg][nt][0], 0.f), fmaxf(acc[rg][nt][1], 0.f));
            if (r2 < n)
                *(__half2*)&h_out[(size_t)r2 * CC + col] =
                    __floats2half2_rn(fmaxf(acc[rg][nt][2], 0.f), fmaxf(acc[rg][nt][3], 0.f));
        }
    }
}

// ---------------- SpMM hop: warp per dst row, fp16, 4 edges per LDG.128 ----------------
// Plain cached loads (best-measured config: L1 reuse on gathers is real).
__device__ __forceinline__ void accum8(float* a, uint4 f, float ww) {
    float2 p0 = __half22float2(*(__half2*)&f.x);
    float2 p1 = __half22float2(*(__half2*)&f.y);
    float2 p2 = __half22float2(*(__half2*)&f.z);
    float2 p3 = __half22float2(*(__half2*)&f.w);
    a[0] = fmaf(ww, p0.x, a[0]); a[1] = fmaf(ww, p0.y, a[1]);
    a[2] = fmaf(ww, p1.x, a[2]); a[3] = fmaf(ww, p1.y, a[3]);
    a[4] = fmaf(ww, p2.x, a[4]); a[5] = fmaf(ww, p2.y, a[5]);
    a[6] = fmaf(ww, p3.x, a[6]); a[7] = fmaf(ww, p3.y, a[7]);
}

__global__ __launch_bounds__(256) void spmm_kernel(const __half* __restrict__ cur,
                                                   __half* __restrict__ nxt, int n) {
    int w = (blockIdx.x * blockDim.x + threadIdx.x) >> 5;
    int lane = threadIdx.x & 31;
    if (w >= n) return;
    int q  = lane >> 3;
    int c8 = (lane & 7) * 8;

    int beg = g_rowptr[w];
    int end = g_rowptr[w + 1];
    float a[8];
#pragma unroll
    for (int i = 0; i < 8; i++) a[i] = 0.f;

    int e = beg;
    for (; e + 7 < end; e += 8) {
        int2 ed0 = g_edges[e + 2 * q];
        int2 ed1 = g_edges[e + 2 * q + 1];
        uint4 f0 = *(const uint4*)&cur[(size_t)ed0.x * CC + c8];
        uint4 f1 = *(const uint4*)&cur[(size_t)ed1.x * CC + c8];
        accum8(a, f0, __int_as_float(ed0.y));
        accum8(a, f1, __int_as_float(ed1.y));
    }
    for (; e < end; e += 4) {
        int myE = e + q;
        if (myE < end) {
            int2 ed = g_edges[myE];
            uint4 f = *(const uint4*)&cur[(size_t)ed.x * CC + c8];
            accum8(a, f, __int_as_float(ed.y));
        }
    }

#pragma unroll
    for (int i = 0; i < 8; i++) {
        a[i] += __shfl_xor_sync(0xffffffffu, a[i], 8);
        a[i] += __shfl_xor_sync(0xffffffffu, a[i], 16);
    }

    if (q == 0) {
        uint4 st;
        *(__half2*)&st.x = __floats2half2_rn(a[0], a[1]);
        *(__half2*)&st.y = __floats2half2_rn(a[2], a[3]);
        *(__half2*)&st.z = __floats2half2_rn(a[4], a[5]);
        *(__half2*)&st.w = __floats2half2_rn(a[6], a[7]);
        *(uint4*)&nxt[(size_t)w * CC + c8] = st;
    }
}

// ---------------- final: lazy hop-10 + gating + gather, requested nodes only ----------------
__global__ void final_kernel(const int* __restrict__ idx,
                             const float* __restrict__ wp,
                             float* __restrict__ out, int ni) {
    int w = (blockIdx.x * blockDim.x + threadIdx.x) >> 5;
    int lane = threadIdx.x & 31;
    if (w >= ni) return;
    int nd = idx[w];
    float wpx = __ldg(&wp[lane * 2]);
    float wpy = __ldg(&wp[lane * 2 + 1]);
    float ax = 0.f, ay = 0.f;

    // hops 0..9 from storage (fp16)
#pragma unroll
    for (int k = 0; k < KHOPS; k++) {
        __half2 vh = *(const __half2*)&g_H[(size_t)k * NN * CC + (size_t)nd * CC + lane * 2];
        float2 v = __half22float2(vh);
        float p = v.x * wpx + v.y * wpy;
#pragma unroll
        for (int o = 16; o; o >>= 1) p += __shfl_xor_sync(0xffffffffu, p, o);
        float s = 1.f / (1.f + __expf(-p));
        ax = fmaf(s, v.x, ax);
        ay = fmaf(s, v.y, ay);
    }

    // hop 10 computed lazily from H[9] (fp16 in, fp32 accum)
    const __half* __restrict__ H9 = g_H + (size_t)(KHOPS - 1) * NN * CC;
    int beg = g_rowptr[nd];
    int end = g_rowptr[nd + 1];
    float a0 = 0.f, a1 = 0.f;
    int e = beg;
    for (; e + 3 < end; e += 4) {
        int2 e0 = g_edges[e];
        int2 e1 = g_edges[e + 1];
        int2 e2 = g_edges[e + 2];
        int2 e3 = g_edges[e + 3];
        float2 v0 = __half22float2(*(const __half2*)&H9[(size_t)e0.x * CC + lane * 2]);
        float2 v1 = __half22float2(*(const __half2*)&H9[(size_t)e1.x * CC + lane * 2]);
        float2 v2 = __half22float2(*(const __half2*)&H9[(size_t)e2.x * CC + lane * 2]);
        float2 v3 = __half22float2(*(const __half2*)&H9[(size_t)e3.x * CC + lane * 2]);
        float w0 = __int_as_float(e0.y);
        float w1 = __int_as_float(e1.y);
        float w2 = __int_as_float(e2.y);
        float w3 = __int_as_float(e3.y);
        a0 = fmaf(w0, v0.x, a0); a1 = fmaf(w0, v0.y, a1);
        a0 = fmaf(w1, v1.x, a0); a1 = fmaf(w1, v1.y, a1);
        a0 = fmaf(w2, v2.x, a0); a1 = fmaf(w2, v2.y, a1);
        a0 = fmaf(w3, v3.x, a0); a1 = fmaf(w3, v3.y, a1);
    }
    for (; e < end; e++) {
        int2 e0 = g_edges[e];
        float2 v0 = __half22float2(*(const __half2*)&H9[(size_t)e0.x * CC + lane * 2]);
        float w0 = __int_as_float(e0.y);
        a0 = fmaf(w0, v0.x, a0); a1 = fmaf(w0, v0.y, a1);
    }
    {
        float p = a0 * wpx + a1 * wpy;
#pragma unroll
        for (int o = 16; o; o >>= 1) p += __shfl_xor_sync(0xffffffffu, p, o);
        float s = 1.f / (1.f + __expf(-p));
        ax = fmaf(s, a0, ax);
        ay = fmaf(s, a1, ay);
    }

    *(float2*)&out[(size_t)w * CC + lane * 2] = make_float2(ax, ay);
}

extern "C" void kernel_launch(void* const* d_in, const int* in_sizes, int n_in,
                              void* d_out, int out_size) {
    const float* x    = (const float*)d_in[0];
    const int*   esrc = (const int*)d_in[1];
    const int*   edst = (const int*)d_in[2];
    const float* ew   = (const float*)d_in[3];
    const int*   nidx = (const int*)d_in[4];
    const float* W1   = (const float*)d_in[5];
    const float* W2   = (const float*)d_in[6];
    const float* wp   = (const float*)d_in[7];

    int N  = in_sizes[0] / DD;
    int E  = in_sizes[1];
    int NI = in_sizes[4];

    __half* H0;
    cudaGetSymbolAddress((void**)&H0, g_H);

    cudaFuncSetAttribute(mlp_mma_kernel,
                         cudaFuncAttributeMaxDynamicSharedMemorySize, MLP_SMEM);

    // one-time resource init (resources only; captured work is identical each call)
    static cudaStream_t s_mlp = nullptr;
    static cudaEvent_t ev_fork = nullptr, ev_join = nullptr;
    if (s_mlp == nullptr) {
        cudaStreamCreateWithFlags(&s_mlp, cudaStreamNonBlocking);
        cudaEventCreateWithFlags(&ev_fork, cudaEventDisableTiming);
        cudaEventCreateWithFlags(&ev_join, cudaEventDisableTiming);
    }

    // fork: MLP on side stream, CSR build on main stream (independent dataflows)
    cudaEventRecord(ev_fork, 0);
    cudaStreamWaitEvent(s_mlp, ev_fork, 0);
    mlp_mma_kernel<<<(N + 255) / 256, 256, MLP_SMEM, s_mlp>>>(x, W1, W2, H0, N);
    cudaEventRecord(ev_join, s_mlp);

    // CSR-by-dst build on main stream
    zero_kernel<<<(N + 255) / 256, 256>>>(N);
    count_kernel<<<(E + 255) / 256, 256>>>(edst, E);
    scan_partial_kernel<<<SCAN_NB, 256>>>(N);
    scan_top_kernel<<<1, 256>>>(SCAN_NB, N);
    rowptr_kernel<<<SCAN_NB, 256>>>(N);
    fill_kernel<<<(E + 255) / 256, 256>>>(esrc, edst, ew, E);

    // join: hops need both CSR and H[0]
    cudaStreamWaitEvent(0, ev_join, 0);

    // 9 full propagation hops: H[k] -> H[k+1] (hop 10 is computed lazily)
    for (int k = 0; k < KHOPS - 1; k++)
        spmm_kernel<<<(N * 32 + 255) / 256, 256>>>(H0 + (size_t)k * NN * CC,
                                                   H0 + (size_t)(k + 1) * NN * CC, N);

    // lazy hop-10 + gating + gather for requested nodes only
    final_kernel<<<(NI * 32 + 255) / 256, 256>>>(nidx, wp, (float*)d_out, NI);
}